// round 12
// baseline (speedup 1.0000x reference)
#include <cuda_runtime.h>
#include <cuda_bf16.h>
#include <cstdint>

#define LEN   2048
#define VOCAB 50000
#define EDIM  256          // embedding dim E (reference: V,E,HID,T = 50000,256,512,12)
#define HDIM  256          // per-direction hidden H = HID/2
#define G4    1024         // 4*H gate rows
#define NTAG  12
#define START_TAG 10
#define STOP_TAG  11
#define NEGV  (-10000.0f)

// ---------------- scratch (static device globals; no allocation) ----------------
__device__ float g_xg[2][LEN][G4];     // x@W_ih^T + (b_ih+b_hh) per direction (16 MB)
__device__ float g_h[LEN][2 * HDIM];   // concatenated hf|hb                    (4 MB)
__device__ float g_feats[LEN][NTAG];   // emission features

// ---------------- helpers ----------------
__device__ __forceinline__ uint32_t smem_u32(const void* p) {
    return (uint32_t)__cvta_generic_to_shared(p);
}
__device__ __forceinline__ float ftanh_fast(float x) {
    float r;
    asm("tanh.approx.f32 %0, %1;" : "=f"(r) : "f"(x));
    return r;
}
__device__ __forceinline__ float fsig_fast(float x) {
    return fmaf(ftanh_fast(0.5f * x), 0.5f, 0.5f);
}
__device__ __forceinline__ unsigned long long packf2_(float lo, float hi) {
    unsigned long long r;
    asm("mov.b64 %0, {%1, %2};" : "=l"(r) : "f"(lo), "f"(hi));
    return r;
}
__device__ __forceinline__ void unpackf2_(unsigned long long v, float& lo, float& hi) {
    asm("mov.b64 {%0, %1}, %2;" : "=f"(lo), "=f"(hi) : "l"(v));
}
__device__ __forceinline__ unsigned long long fma2_(
    unsigned long long a, unsigned long long b, unsigned long long c) {
    unsigned long long r;
    asm("fma.rn.f32x2 %0, %1, %2, %3;" : "=l"(r) : "l"(a), "l"(b), "l"(c));
    return r;
}

#define MBARRIER_INIT(mbar_addr, count) \
    asm volatile("mbarrier.init.shared.b64 [%0], %1;" \
                 :: "r"((uint32_t)(mbar_addr)), "r"((uint32_t)(count)) : "memory")

// Plain remote arrive (pre-loop; ordering provided by prior cluster barrier)
#define MBARRIER_ARRIVE_CLUSTER(local_mbar_addr, target_rank) \
    asm volatile( \
        "{\n\t" \
        ".reg .b32 remAddr32;\n\t" \
        "mapa.shared::cluster.u32 remAddr32, %0, %1;\n\t" \
        "mbarrier.arrive.shared::cluster.b64 _, [remAddr32];\n\t" \
        "}" \
        :: "r"((uint32_t)(local_mbar_addr)), "r"((uint32_t)(target_rank)) : "memory")

// Release arrive: orders this thread's (and, after __syncwarp, this warp's)
// prior shared::cluster stores before the arrival is observed.
#define MBARRIER_ARRIVE_RELEASE_CLUSTER(local_mbar_addr, target_rank) \
    asm volatile( \
        "{\n\t" \
        ".reg .b32 remAddr32;\n\t" \
        "mapa.shared::cluster.u32 remAddr32, %0, %1;\n\t" \
        "mbarrier.arrive.release.cluster.shared::cluster.b64 _, [remAddr32];\n\t" \
        "}" \
        :: "r"((uint32_t)(local_mbar_addr)), "r"((uint32_t)(target_rank)) : "memory")

// Cluster-scope acquire wait (pairs with the release arrives above)
#define MBARRIER_WAIT_PARITY_CL(mbar_smem_addr, phase_parity) do { \
    uint32_t _mbar = (uint32_t)(mbar_smem_addr); \
    uint32_t _parity = (uint32_t)(phase_parity); \
    uint32_t _done; \
    asm volatile( \
        "{\n\t" \
        ".reg .pred p;\n\t" \
        "mbarrier.try_wait.parity.acquire.cluster.shared::cta.b64 p, [%1], %2;\n\t" \
        "selp.b32 %0, 1, 0, p;\n\t" \
        "}" \
        : "=r"(_done) : "r"(_mbar), "r"(_parity) : "memory"); \
    if (!_done) { \
        asm volatile( \
            "{\n\t" \
            ".reg .pred P1;\n\t" \
            "WAIT_LOOP_%=:\n\t" \
            "mbarrier.try_wait.parity.acquire.cluster.shared::cta.b64 P1, [%0], %1, 0x989680;\n\t" \
            "@P1 bra.uni WAIT_DONE_%=;\n\t" \
            "bra.uni WAIT_LOOP_%=;\n\t" \
            "WAIT_DONE_%=:\n\t" \
            "}" \
            :: "r"(_mbar), "r"(_parity) : "memory"); \
    } \
} while(0)

// ================= Kernel 1: xg = embed[sentence] @ W_ih^T + (b_ih + b_hh) =========
__global__ void __launch_bounds__(256) xg_gemm(
    const int* __restrict__ sent, const float* __restrict__ embed,
    const float* __restrict__ w_f, const float* __restrict__ w_b,
    const float* __restrict__ bi_f, const float* __restrict__ bh_f,
    const float* __restrict__ bi_b, const float* __restrict__ bh_b)
{
    const int dir = blockIdx.z;
    const float* __restrict__ W = dir ? w_b : w_f;   // [1024][256]
    const int t0 = blockIdx.x * 64;
    const int r0 = blockIdx.y * 64;

    __shared__ __align__(16) float xs[32][68];
    __shared__ __align__(16) float ws[32][68];
    __shared__ int   sidx[64];

    const int tid = threadIdx.x;
    if (tid < 64) {
        int v = sent[t0 + tid];
        v = v < 0 ? 0 : (v >= VOCAB ? VOCAB - 1 : v);
        sidx[tid] = v;
    }
    __syncthreads();

    float acc[4][4];
#pragma unroll
    for (int i = 0; i < 4; i++)
#pragma unroll
        for (int j = 0; j < 4; j++) acc[i][j] = 0.f;

    const int ty = tid >> 4;
    const int tx = tid & 15;

    for (int k0 = 0; k0 < EDIM; k0 += 32) {
#pragma unroll
        for (int i = 0; i < 8; i++) {
            int idx = i * 256 + tid;
            int a = idx >> 5, kk = idx & 31;
            xs[kk][a] = embed[(long)sidx[a] * EDIM + k0 + kk];
            ws[kk][a] = W[(long)(r0 + a) * EDIM + k0 + kk];
        }
        __syncthreads();
#pragma unroll
        for (int kk = 0; kk < 32; kk++) {
            float4 xv = *(const float4*)&xs[kk][ty * 4];
            float4 wv = *(const float4*)&ws[kk][tx * 4];
            float xa[4] = {xv.x, xv.y, xv.z, xv.w};
            float wa[4] = {wv.x, wv.y, wv.z, wv.w};
#pragma unroll
            for (int i = 0; i < 4; i++)
#pragma unroll
                for (int j = 0; j < 4; j++) acc[i][j] += xa[i] * wa[j];
        }
        __syncthreads();
    }

    const float* __restrict__ bi = dir ? bi_b : bi_f;
    const float* __restrict__ bh = dir ? bh_b : bh_f;
#pragma unroll
    for (int j = 0; j < 4; j++) {
        int row = r0 + tx * 4 + j;
        float b = bi[row] + bh[row];
#pragma unroll
        for (int i = 0; i < 4; i++) {
            int t = t0 + ty * 4 + i;
            g_xg[dir][t][row] = acc[i][j] + b;
        }
    }
}

// ================= Kernel 2: bidirectional LSTM recurrence ========================
// 2 clusters of 8 CTAs. tid = k*16 + seg. Per step: wait(mbar[s&3], acquire.cluster)
// -> f32x2 dot on hbuf[s&1] -> 16-lane reduce -> seg==0: activation + DSMEM
// multicast into hbuf[(s+1)&1] -> __syncwarp -> lane0: 8 release-arrives at
// mbar[(s+1)&3]. No __syncthreads, no cluster fence. mbar count = 128
// (16 warps x 8 CTAs); each warp's arrive certifies its reads finished.
__global__ void __cluster_dims__(8, 1, 1) __launch_bounds__(512, 1)
lstm_kernel(const float* __restrict__ whh_f, const float* __restrict__ whh_b)
{
    const int dir = blockIdx.x >> 3;
    unsigned rank;
    asm("mov.u32 %0, %%cluster_ctarank;" : "=r"(rank));
    const float* __restrict__ Whh = dir ? whh_b : whh_f;

    const int tid  = threadIdx.x;     // 0..511
    const int k    = tid >> 4;        // local h-index 0..31
    const int seg  = tid & 15;        // 16-column segment
    const int lane = tid & 31;
    const int kg   = (int)rank * 32 + k;

    // weights -> registers (32 f32x2 = 64 regs)
    unsigned long long wd[4][8];
#pragma unroll
    for (int u = 0; u < 4; u++) {
        const float4* wp = (const float4*)(Whh + (long)(u * HDIM + kg) * HDIM + seg * 16);
#pragma unroll
        for (int i = 0; i < 4; i++) {
            float4 v = wp[i];
            wd[u][2 * i + 0] = packf2_(v.x, v.y);
            wd[u][2 * i + 1] = packf2_(v.z, v.w);
        }
    }

    __shared__ __align__(16) float hbuf[2][HDIM];
    __shared__ __align__(8) unsigned long long mbar[4];
    if (tid < HDIM) hbuf[0][tid] = 0.f;
    if (tid == 0) {
#pragma unroll
        for (int i = 0; i < 4; i++)
            MBARRIER_INIT(smem_u32(&mbar[i]), 128);
    }
    __syncthreads();

    // all CTAs: smem + mbar init visible cluster-wide before any DSMEM traffic
    asm volatile("barrier.cluster.arrive.aligned;" ::: "memory");
    asm volatile("barrier.cluster.wait.aligned;"   ::: "memory");

    const uint32_t mb0 = smem_u32(&mbar[0]);
    const uint32_t mb1 = smem_u32(&mbar[1]);
    const uint32_t mb2 = smem_u32(&mbar[2]);
    const uint32_t mb3 = smem_u32(&mbar[3]);
    const uint32_t h_l0 = smem_u32(&hbuf[0][kg]);
    const uint32_t h_l1 = smem_u32(&hbuf[1][kg]);

    // step-0 arrivals: one per warp per peer (h=0 ordered by cluster barrier)
    if (lane == 0) {
#pragma unroll
        for (int peer = 0; peer < 8; peer++)
            MBARRIER_ARRIVE_CLUSTER(mb0, peer);
    }

    float cstate = 0.f;
    const float* __restrict__ xg = &g_xg[dir][0][0];

    for (int step = 0; step < LEN; step++) {
        const int t = dir ? (LEN - 1 - step) : step;

        // prefetch this step's x-gate values (no h dependency; completes in wait)
        float xv0 = 0.f, xv1 = 0.f, xv2 = 0.f, xv3 = 0.f;
        if (seg == 0) {
            const float* xr = &xg[(long)t * G4 + kg];
            xv0 = __ldg(xr);
            xv1 = __ldg(xr + HDIM);
            xv2 = __ldg(xr + 2 * HDIM);
            xv3 = __ldg(xr + 3 * HDIM);
        }

        uint32_t mb = (step & 3) == 0 ? mb0 : (step & 3) == 1 ? mb1
                     : (step & 3) == 2 ? mb2 : mb3;
        MBARRIER_WAIT_PARITY_CL(mb, (step >> 2) & 1);

        const int buf = step & 1;
        unsigned long long acc0 = 0ull, acc1 = 0ull, acc2 = 0ull, acc3 = 0ull;
        const ulonglong2* hp = (const ulonglong2*)&hbuf[buf][seg * 16];
#pragma unroll
        for (int i = 0; i < 4; i++) {
            ulonglong2 hv = hp[i];
            acc0 = fma2_(wd[0][2 * i], hv.x, acc0);
            acc1 = fma2_(wd[1][2 * i], hv.x, acc1);
            acc2 = fma2_(wd[2][2 * i], hv.x, acc2);
            acc3 = fma2_(wd[3][2 * i], hv.x, acc3);
            acc0 = fma2_(wd[0][2 * i + 1], hv.y, acc0);
            acc1 = fma2_(wd[1][2 * i + 1], hv.y, acc1);
            acc2 = fma2_(wd[2][2 * i + 1], hv.y, acc2);
            acc3 = fma2_(wd[3][2 * i + 1], hv.y, acc3);
        }
        float lo, hi, s0, s1, s2, s3;
        unpackf2_(acc0, lo, hi); s0 = lo + hi;
        unpackf2_(acc1, lo, hi); s1 = lo + hi;
        unpackf2_(acc2, lo, hi); s2 = lo + hi;
        unpackf2_(acc3, lo, hi); s3 = lo + hi;

#pragma unroll
        for (int m = 1; m < 16; m <<= 1) {
            s0 += __shfl_xor_sync(0xffffffffu, s0, m);
            s1 += __shfl_xor_sync(0xffffffffu, s1, m);
            s2 += __shfl_xor_sync(0xffffffffu, s2, m);
            s3 += __shfl_xor_sync(0xffffffffu, s3, m);
        }

        if (seg == 0) {
            float gi = s0 + xv0;
            float gf = s1 + xv1;
            float gg = s2 + xv2;
            float go = s3 + xv3;
            float ii = fsig_fast(gi), ff = fsig_fast(gf), oo = fsig_fast(go);
            cstate = ff * cstate + ii * ftanh_fast(gg);
            float h = oo * ftanh_fast(cstate);

            if (step != LEN - 1) {
                uint32_t dst = (buf ^ 1) ? h_l1 : h_l0;
#pragma unroll
                for (int peer = 0; peer < 8; peer++) {
                    uint32_t rem;
                    asm volatile("mapa.shared::cluster.u32 %0, %1, %2;"
                                 : "=r"(rem) : "r"(dst), "r"(peer));
                    asm volatile("st.shared::cluster.f32 [%0], %1;"
                                 :: "r"(rem), "f"(h) : "memory");
                }
            }
            g_h[t][dir * HDIM + kg] = h;
        }

        if (step != LEN - 1) {
            __syncwarp();                      // warp-internal happens-before
            if (lane == 0) {
                uint32_t mbn = ((step + 1) & 3) == 0 ? mb0 : ((step + 1) & 3) == 1 ? mb1
                              : ((step + 1) & 3) == 2 ? mb2 : mb3;
#pragma unroll
                for (int peer = 0; peer < 8; peer++)
                    MBARRIER_ARRIVE_RELEASE_CLUSTER(mbn, peer);
            }
        }
    }
}

// ================= Kernel 3: feats = h @ w_out^T + b_out =================
__global__ void __launch_bounds__(256) feats_kernel(
    const float* __restrict__ w_out, const float* __restrict__ b_out)
{
    __shared__ __align__(16) float hs[16][2 * HDIM];
    const int t0 = blockIdx.x * 16;
    const int tid = threadIdx.x;

    const float* src = &g_h[t0][0];
#pragma unroll
    for (int i = 0; i < 32; i++) {
        int idx = i * 256 + tid;
        ((float*)hs)[idx] = src[idx];
    }
    __syncthreads();

    if (tid < 192) {
        int tt = tid / NTAG, tg = tid % NTAG;
        const float4* h4 = (const float4*)hs[tt];
        const float4* w4 = (const float4*)(w_out + (long)tg * (2 * HDIM));
        float s = 0.f;
#pragma unroll 8
        for (int kk = 0; kk < (2 * HDIM) / 4; kk++) {
            float4 a = h4[kk];
            float4 b = w4[kk];
            s += a.x * b.x + a.y * b.y + a.z * b.z + a.w * b.w;
        }
        g_feats[t0 + tt][tg] = s + b_out[tg];
    }
}

// ================= Kernel 4: Viterbi forward + backtrack (1 warp) =================
// Replicated v in registers, fmaxf tree, argmax off-path, depth-2 feat prefetch
// so the ~250-cycle L2 latency is covered by two loop iterations.
__global__ void __launch_bounds__(32) viterbi_kernel(
    const float* __restrict__ trans, float* __restrict__ out, int out_cap)
{
    __shared__ unsigned char bp[LEN][NTAG];
    const int lane = threadIdx.x;
    const bool act = lane < NTAG;
    const int ln = act ? lane : (NTAG - 1);      // clamp: speculated loads stay in-bounds

    float Trow[NTAG];
#pragma unroll
    for (int j = 0; j < NTAG; j++)
        Trow[j] = trans[ln * NTAG + j];

    float v[NTAG];
#pragma unroll
    for (int j = 0; j < NTAG; j++)
        v[j] = (j == START_TAG) ? 0.f : NEGV;

    float feat  = g_feats[0][ln];
    float featn = g_feats[1][ln];

    for (int t = 0; t < LEN; t++) {
        int t2 = (t + 2 < LEN) ? (t + 2) : (LEN - 1);
        float feat2 = g_feats[t2][ln];           // consumed 2 iterations later

        float cand[NTAG];
#pragma unroll
        for (int j = 0; j < NTAG; j++) cand[j] = v[j] + Trow[j];

        float m0 = fmaxf(cand[0], cand[1]);
        float m1 = fmaxf(cand[2], cand[3]);
        float m2 = fmaxf(cand[4], cand[5]);
        float m3 = fmaxf(cand[6], cand[7]);
        float m4 = fmaxf(cand[8], cand[9]);
        float m5 = fmaxf(cand[10], cand[11]);
        float n0 = fmaxf(m0, m1);
        float n1 = fmaxf(m2, m3);
        float n2 = fmaxf(m4, m5);
        float best = fmaxf(fmaxf(n0, n1), n2);

        float vl = best + feat;

        int bj = NTAG - 1;
#pragma unroll
        for (int j = NTAG - 1; j >= 0; j--)
            if (cand[j] == best) bj = j;
        if (act) bp[t][lane] = (unsigned char)bj;

#pragma unroll
        for (int j = 0; j < NTAG; j++)
            v[j] = __shfl_sync(0xffffffffu, vl, j);

        feat = featn;
        featn = feat2;
    }

    float tv = act ? (v[ln] + trans[STOP_TAG * NTAG + ln]) : -3.4e38f;
    int ti = lane;
#pragma unroll
    for (int off = 16; off >= 1; off >>= 1) {
        float ov = __shfl_xor_sync(0xffffffffu, tv, off);
        int   oi = __shfl_xor_sync(0xffffffffu, ti, off);
        if (ov > tv || (ov == tv && oi < ti)) { tv = ov; ti = oi; }
    }

    if (lane == 0) {
        if (out_cap > 0) out[0] = tv;
        int tag = ti;
        for (int t = LEN - 1; t >= 0; t--) {
            if (1 + t < out_cap) out[1 + t] = (float)tag;
            tag = bp[t][tag];
        }
    }
}

// ================= launch =================
extern "C" void kernel_launch(void* const* d_in, const int* in_sizes, int n_in,
                              void* d_out, int out_size)
{
    const int*   sentence = (const int*)  d_in[0];
    const float* embed    = (const float*)d_in[1];
    const float* w_ih_f   = (const float*)d_in[2];
    const float* w_hh_f   = (const float*)d_in[3];
    const float* b_ih_f   = (const float*)d_in[4];
    const float* b_hh_f   = (const float*)d_in[5];
    const float* w_ih_b   = (const float*)d_in[6];
    const float* w_hh_b   = (const float*)d_in[7];
    const float* b_ih_b   = (const float*)d_in[8];
    const float* b_hh_b   = (const float*)d_in[9];
    const float* w_out    = (const float*)d_in[10];
    const float* b_out    = (const float*)d_in[11];
    const float* trans    = (const float*)d_in[12];

    int out_cap = out_size < (LEN + 1) ? out_size : (LEN + 1);

    xg_gemm<<<dim3(LEN / 64, G4 / 64, 2), 256>>>(sentence, embed,
                                                 w_ih_f, w_ih_b,
                                                 b_ih_f, b_hh_f, b_ih_b, b_hh_b);
    lstm_kernel<<<16, 512>>>(w_hh_f, w_hh_b);
    feats_kernel<<<LEN / 16, 256>>>(w_out, b_out);
    viterbi_kernel<<<1, 32>>>(trans, (float*)d_out, out_cap);
}

// round 13
// speedup vs baseline: 3.0446x; 3.0446x over previous
#include <cuda_runtime.h>
#include <cuda_bf16.h>
#include <cstdint>

#define LEN   2048
#define VOCAB 50000
#define EDIM  256          // embedding dim E (reference: V,E,HID,T = 50000,256,512,12)
#define HDIM  256          // per-direction hidden H = HID/2
#define G4    1024         // 4*H gate rows
#define NTAG  12
#define START_TAG 10
#define STOP_TAG  11
#define NEGV  (-10000.0f)

// ---------------- scratch (static device globals; no allocation) ----------------
__device__ float g_xg[2][LEN][G4];                 // x@W_ih^T + bias (16 MB)
__device__ float g_h[LEN][2 * HDIM];               // concatenated hf|hb (4 MB)
__device__ __align__(16) float g_feats[LEN][NTAG]; // emission features

// ---------------- helpers ----------------
__device__ __forceinline__ uint32_t smem_u32(const void* p) {
    return (uint32_t)__cvta_generic_to_shared(p);
}
__device__ __forceinline__ float ftanh_fast(float x) {
    float r;
    asm("tanh.approx.f32 %0, %1;" : "=f"(r) : "f"(x));
    return r;
}
__device__ __forceinline__ float fsig_fast(float x) {
    return fmaf(ftanh_fast(0.5f * x), 0.5f, 0.5f);
}
__device__ __forceinline__ unsigned long long packf2_(float lo, float hi) {
    unsigned long long r;
    asm("mov.b64 %0, {%1, %2};" : "=l"(r) : "f"(lo), "f"(hi));
    return r;
}
__device__ __forceinline__ void unpackf2_(unsigned long long v, float& lo, float& hi) {
    asm("mov.b64 {%0, %1}, %2;" : "=f"(lo), "=f"(hi) : "l"(v));
}
__device__ __forceinline__ unsigned long long fma2_(
    unsigned long long a, unsigned long long b, unsigned long long c) {
    unsigned long long r;
    asm("fma.rn.f32x2 %0, %1, %2, %3;" : "=l"(r) : "l"(a), "l"(b), "l"(c));
    return r;
}

#define MBARRIER_INIT(mbar_addr, count) \
    asm volatile("mbarrier.init.shared.b64 [%0], %1;" \
                 :: "r"((uint32_t)(mbar_addr)), "r"((uint32_t)(count)) : "memory")

// Plain local arrive (used to pre-complete mbar[0]'s phase 0)
#define MBARRIER_ARRIVE_LOCAL(mbar_addr) \
    asm volatile("mbarrier.arrive.shared.b64 _, [%0];" \
                 :: "r"((uint32_t)(mbar_addr)) : "memory")

// Arm: one arrival + expect tx bytes for the current phase
#define MBARRIER_ARM_TX(mbar_addr, txbytes) \
    asm volatile("mbarrier.arrive.expect_tx.shared.b64 _, [%0], %1;" \
                 :: "r"((uint32_t)(mbar_addr)), "r"((uint32_t)(txbytes)) : "memory")

// Async remote store: writes 4B into peer's smem and completes tx on the
// mbarrier in the SAME (peer) CTA. Data movement carries the sync.
#define ST_ASYNC_U32(local_dst, local_mbar, peer, val) \
    asm volatile( \
        "{\n\t" \
        ".reg .b32 rd, rm;\n\t" \
        "mapa.shared::cluster.u32 rd, %0, %2;\n\t" \
        "mapa.shared::cluster.u32 rm, %1, %2;\n\t" \
        "st.async.shared::cluster.mbarrier::complete_tx::bytes.u32 [rd], %3, [rm];\n\t" \
        "}" \
        :: "r"((uint32_t)(local_dst)), "r"((uint32_t)(local_mbar)), \
           "r"((uint32_t)(peer)), "r"((uint32_t)(val)) : "memory")

// Acquire wait on local mbar phase parity (HW sleep)
#define MBARRIER_WAIT_PARITY(mbar_smem_addr, phase_parity) do { \
    uint32_t _mbar = (uint32_t)(mbar_smem_addr); \
    uint32_t _parity = (uint32_t)(phase_parity); \
    uint32_t _done; \
    asm volatile( \
        "{\n\t" \
        ".reg .pred p;\n\t" \
        "mbarrier.try_wait.parity.acquire.cta.shared::cta.b64 p, [%1], %2;\n\t" \
        "selp.b32 %0, 1, 0, p;\n\t" \
        "}" \
        : "=r"(_done) : "r"(_mbar), "r"(_parity) : "memory"); \
    if (!_done) { \
        asm volatile( \
            "{\n\t" \
            ".reg .pred P1;\n\t" \
            "WAIT_LOOP_%=:\n\t" \
            "mbarrier.try_wait.parity.acquire.cta.shared::cta.b64 P1, [%0], %1, 0x989680;\n\t" \
            "@P1 bra.uni WAIT_DONE_%=;\n\t" \
            "bra.uni WAIT_LOOP_%=;\n\t" \
            "WAIT_DONE_%=:\n\t" \
            "}" \
            :: "r"(_mbar), "r"(_parity) : "memory"); \
    } \
} while(0)

// ================= Kernel 1: xg = embed[sentence] @ W_ih^T + (b_ih + b_hh) =========
__global__ void __launch_bounds__(256) xg_gemm(
    const int* __restrict__ sent, const float* __restrict__ embed,
    const float* __restrict__ w_f, const float* __restrict__ w_b,
    const float* __restrict__ bi_f, const float* __restrict__ bh_f,
    const float* __restrict__ bi_b, const float* __restrict__ bh_b)
{
    const int dir = blockIdx.z;
    const float* __restrict__ W = dir ? w_b : w_f;   // [1024][256]
    const int t0 = blockIdx.x * 64;
    const int r0 = blockIdx.y * 64;

    __shared__ __align__(16) float xs[32][68];
    __shared__ __align__(16) float ws[32][68];
    __shared__ int   sidx[64];

    const int tid = threadIdx.x;
    if (tid < 64) {
        int v = sent[t0 + tid];
        v = v < 0 ? 0 : (v >= VOCAB ? VOCAB - 1 : v);
        sidx[tid] = v;
    }
    __syncthreads();

    float acc[4][4];
#pragma unroll
    for (int i = 0; i < 4; i++)
#pragma unroll
        for (int j = 0; j < 4; j++) acc[i][j] = 0.f;

    const int ty = tid >> 4;
    const int tx = tid & 15;

    for (int k0 = 0; k0 < EDIM; k0 += 32) {
#pragma unroll
        for (int i = 0; i < 8; i++) {
            int idx = i * 256 + tid;
            int a = idx >> 5, kk = idx & 31;
            xs[kk][a] = embed[(long)sidx[a] * EDIM + k0 + kk];
            ws[kk][a] = W[(long)(r0 + a) * EDIM + k0 + kk];
        }
        __syncthreads();
#pragma unroll
        for (int kk = 0; kk < 32; kk++) {
            float4 xv = *(const float4*)&xs[kk][ty * 4];
            float4 wv = *(const float4*)&ws[kk][tx * 4];
            float xa[4] = {xv.x, xv.y, xv.z, xv.w};
            float wa[4] = {wv.x, wv.y, wv.z, wv.w};
#pragma unroll
            for (int i = 0; i < 4; i++)
#pragma unroll
                for (int j = 0; j < 4; j++) acc[i][j] += xa[i] * wa[j];
        }
        __syncthreads();
    }

    const float* __restrict__ bi = dir ? bi_b : bi_f;
    const float* __restrict__ bh = dir ? bh_b : bh_f;
#pragma unroll
    for (int j = 0; j < 4; j++) {
        int row = r0 + tx * 4 + j;
        float b = bi[row] + bh[row];
#pragma unroll
        for (int i = 0; i < 4; i++) {
            int t = t0 + ty * 4 + i;
            g_xg[dir][t][row] = acc[i][j] + b;
        }
    }
}

// ================= Kernel 2: bidirectional LSTM recurrence (st.async) =============
// 2 clusters of 8 CTAs. tid = k*16 + seg. Per step s: wait(mbar[s&3], parity
// (s>>2)&1) -> f32x2 dot on hbuf[s&1] -> 16-lane reduce -> seg==0: activation +
// 8x st.async h into peers' hbuf[(s+1)&1], each completing 4B of tx on the
// peer's mbar[(s+1)&3]. tid0 arms mbar[(s+3)&3] (expect_tx 1024 = 256 floats).
// No __syncthreads, no cluster fence, no separate arrives: the stores ARE the sync.
__global__ void __cluster_dims__(8, 1, 1) __launch_bounds__(512, 1)
lstm_kernel(const float* __restrict__ whh_f, const float* __restrict__ whh_b)
{
    const int dir = blockIdx.x >> 3;
    unsigned rank;
    asm("mov.u32 %0, %%cluster_ctarank;" : "=r"(rank));
    const float* __restrict__ Whh = dir ? whh_b : whh_f;

    const int tid = threadIdx.x;      // 0..511
    const int k   = tid >> 4;         // local h-index 0..31
    const int seg = tid & 15;         // 16-column segment
    const int kg  = (int)rank * 32 + k;

    // weights -> registers (32 f32x2 = 64 regs)
    unsigned long long wd[4][8];
#pragma unroll
    for (int u = 0; u < 4; u++) {
        const float4* wp = (const float4*)(Whh + (long)(u * HDIM + kg) * HDIM + seg * 16);
#pragma unroll
        for (int i = 0; i < 4; i++) {
            float4 v = wp[i];
            wd[u][2 * i + 0] = packf2_(v.x, v.y);
            wd[u][2 * i + 1] = packf2_(v.z, v.w);
        }
    }

    __shared__ __align__(16) float hbuf[2][HDIM];
    __shared__ __align__(8) unsigned long long mbar[4];
    if (tid < HDIM) hbuf[0][tid] = 0.f;
    if (tid == 0) {
#pragma unroll
        for (int i = 0; i < 4; i++)
            MBARRIER_INIT(smem_u32(&mbar[i]), 1);
        // mbar[0]: pre-complete phase 0 (h=0 is locally initialized)
        MBARRIER_ARRIVE_LOCAL(smem_u32(&mbar[0]));
        // mbar[1], mbar[2]: armed for steps 1 and 2 (stores during steps 0 and 1)
        MBARRIER_ARM_TX(smem_u32(&mbar[1]), HDIM * 4);
        MBARRIER_ARM_TX(smem_u32(&mbar[2]), HDIM * 4);
    }
    __syncthreads();

    // cluster-wide: all inits/arms visible before any st.async traffic
    asm volatile("barrier.cluster.arrive.aligned;" ::: "memory");
    asm volatile("barrier.cluster.wait.aligned;"   ::: "memory");

    const uint32_t mb0 = smem_u32(&mbar[0]);
    const uint32_t mb1 = smem_u32(&mbar[1]);
    const uint32_t mb2 = smem_u32(&mbar[2]);
    const uint32_t mb3 = smem_u32(&mbar[3]);
    const uint32_t h_l0 = smem_u32(&hbuf[0][kg]);
    const uint32_t h_l1 = smem_u32(&hbuf[1][kg]);

    float cstate = 0.f;
    const float* __restrict__ xg = &g_xg[dir][0][0];

    for (int step = 0; step < LEN; step++) {
        const int t = dir ? (LEN - 1 - step) : step;

        // prefetch this step's x-gate values (no h dependency; completes in wait)
        float xv0 = 0.f, xv1 = 0.f, xv2 = 0.f, xv3 = 0.f;
        if (seg == 0) {
            const float* xr = &xg[(long)t * G4 + kg];
            xv0 = __ldg(xr);
            xv1 = __ldg(xr + HDIM);
            xv2 = __ldg(xr + 2 * HDIM);
            xv3 = __ldg(xr + 3 * HDIM);
        }

        uint32_t mb = (step & 3) == 0 ? mb0 : (step & 3) == 1 ? mb1
                     : (step & 3) == 2 ? mb2 : mb3;
        MBARRIER_WAIT_PARITY(mb, (step >> 2) & 1);

        // arm 3 steps ahead (earliest store for step+3 lands >= 2 full steps later)
        if (tid == 0 && step + 3 < LEN) {
            uint32_t mba = ((step + 3) & 3) == 0 ? mb0 : ((step + 3) & 3) == 1 ? mb1
                          : ((step + 3) & 3) == 2 ? mb2 : mb3;
            MBARRIER_ARM_TX(mba, HDIM * 4);
        }

        const int buf = step & 1;
        unsigned long long acc0 = 0ull, acc1 = 0ull, acc2 = 0ull, acc3 = 0ull;
        const ulonglong2* hp = (const ulonglong2*)&hbuf[buf][seg * 16];
#pragma unroll
        for (int i = 0; i < 4; i++) {
            ulonglong2 hv = hp[i];
            acc0 = fma2_(wd[0][2 * i], hv.x, acc0);
            acc1 = fma2_(wd[1][2 * i], hv.x, acc1);
            acc2 = fma2_(wd[2][2 * i], hv.x, acc2);
            acc3 = fma2_(wd[3][2 * i], hv.x, acc3);
            acc0 = fma2_(wd[0][2 * i + 1], hv.y, acc0);
            acc1 = fma2_(wd[1][2 * i + 1], hv.y, acc1);
            acc2 = fma2_(wd[2][2 * i + 1], hv.y, acc2);
            acc3 = fma2_(wd[3][2 * i + 1], hv.y, acc3);
        }
        float lo, hi, s0, s1, s2, s3;
        unpackf2_(acc0, lo, hi); s0 = lo + hi;
        unpackf2_(acc1, lo, hi); s1 = lo + hi;
        unpackf2_(acc2, lo, hi); s2 = lo + hi;
        unpackf2_(acc3, lo, hi); s3 = lo + hi;

#pragma unroll
        for (int m = 1; m < 16; m <<= 1) {
            s0 += __shfl_xor_sync(0xffffffffu, s0, m);
            s1 += __shfl_xor_sync(0xffffffffu, s1, m);
            s2 += __shfl_xor_sync(0xffffffffu, s2, m);
            s3 += __shfl_xor_sync(0xffffffffu, s3, m);
        }

        if (seg == 0) {
            float gi = s0 + xv0;
            float gf = s1 + xv1;
            float gg = s2 + xv2;
            float go = s3 + xv3;
            float ii = fsig_fast(gi), ff = fsig_fast(gf), oo = fsig_fast(go);
            cstate = ff * cstate + ii * ftanh_fast(gg);
            float h = oo * ftanh_fast(cstate);

            if (step != LEN - 1) {
                uint32_t dst = (buf ^ 1) ? h_l1 : h_l0;
                uint32_t mbn = ((step + 1) & 3) == 0 ? mb0 : ((step + 1) & 3) == 1 ? mb1
                              : ((step + 1) & 3) == 2 ? mb2 : mb3;
                uint32_t hv = __float_as_uint(h);
#pragma unroll
                for (int peer = 0; peer < 8; peer++)
                    ST_ASYNC_U32(dst, mbn, peer, hv);
            }
            g_h[t][dir * HDIM + kg] = h;
        }
    }
}

// ================= Kernel 3: feats = h @ w_out^T + b_out =================
__global__ void __launch_bounds__(256) feats_kernel(
    const float* __restrict__ w_out, const float* __restrict__ b_out)
{
    __shared__ __align__(16) float hs[16][2 * HDIM];
    const int t0 = blockIdx.x * 16;
    const int tid = threadIdx.x;

    const float* src = &g_h[t0][0];
#pragma unroll
    for (int i = 0; i < 32; i++) {
        int idx = i * 256 + tid;
        ((float*)hs)[idx] = src[idx];
    }
    __syncthreads();

    if (tid < 192) {
        int tt = tid / NTAG, tg = tid % NTAG;
        const float4* h4 = (const float4*)hs[tt];
        const float4* w4 = (const float4*)(w_out + (long)tg * (2 * HDIM));
        float s = 0.f;
#pragma unroll 8
        for (int kk = 0; kk < (2 * HDIM) / 4; kk++) {
            float4 a = h4[kk];
            float4 b = w4[kk];
            s += a.x * b.x + a.y * b.y + a.z * b.z + a.w * b.w;
        }
        g_feats[t0 + tt][tg] = s + b_out[tg];
    }
}

// ================= Kernel 4: Viterbi forward + backtrack (1 warp, smem feats) =====
// All emission features staged into dynamic smem once (~96 KB), so the per-step
// feat access is an LDS (29 cyc) instead of an L2 LDG (~250 cyc).
__global__ void __launch_bounds__(32) viterbi_kernel(
    const float* __restrict__ trans, float* __restrict__ out, int out_cap)
{
    extern __shared__ float fs[];                // [LEN * NTAG] staged feats
    __shared__ unsigned char bp[LEN][NTAG];      // backpointers (24 KB)
    const int lane = threadIdx.x;
    const bool act = lane < NTAG;
    const int ln = act ? lane : (NTAG - 1);      // clamp: speculated loads stay in-bounds

    // stage feats (6144 float4 loads, coalesced)
    {
        const float4* src = (const float4*)&g_feats[0][0];
        float4* d4 = (float4*)fs;
        for (int i = lane; i < (LEN * NTAG) / 4; i += 32) d4[i] = src[i];
    }
    __syncwarp();

    float Trow[NTAG];
#pragma unroll
    for (int j = 0; j < NTAG; j++)
        Trow[j] = trans[ln * NTAG + j];

    float v[NTAG];
#pragma unroll
    for (int j = 0; j < NTAG; j++)
        v[j] = (j == START_TAG) ? 0.f : NEGV;

    float feat = fs[0 * NTAG + ln];

    for (int t = 0; t < LEN; t++) {
        int tn = (t + 1 < LEN) ? (t + 1) : t;
        float featn = fs[tn * NTAG + ln];        // LDS prefetch, off critical path

        float cand[NTAG];
#pragma unroll
        for (int j = 0; j < NTAG; j++) cand[j] = v[j] + Trow[j];

        float m0 = fmaxf(cand[0], cand[1]);
        float m1 = fmaxf(cand[2], cand[3]);
        float m2 = fmaxf(cand[4], cand[5]);
        float m3 = fmaxf(cand[6], cand[7]);
        float m4 = fmaxf(cand[8], cand[9]);
        float m5 = fmaxf(cand[10], cand[11]);
        float n0 = fmaxf(m0, m1);
        float n1 = fmaxf(m2, m3);
        float n2 = fmaxf(m4, m5);
        float best = fmaxf(fmaxf(n0, n1), n2);

        float vl = best + feat;

        int bj = NTAG - 1;                        // first-max argmax, off-path
#pragma unroll
        for (int j = NTAG - 1; j >= 0; j--)
            if (cand[j] == best) bj = j;
        if (act) bp[t][lane] = (unsigned char)bj;

#pragma unroll
        for (int j = 0; j < NTAG; j++)
            v[j] = __shfl_sync(0xffffffffu, vl, j);

        feat = featn;
    }

    float tv = act ? (v[ln] + trans[STOP_TAG * NTAG + ln]) : -3.4e38f;
    int ti = lane;
#pragma unroll
    for (int off = 16; off >= 1; off >>= 1) {
        float ov = __shfl_xor_sync(0xffffffffu, tv, off);
        int   oi = __shfl_xor_sync(0xffffffffu, ti, off);
        if (ov > tv || (ov == tv && oi < ti)) { tv = ov; ti = oi; }
    }

    if (lane == 0) {
        if (out_cap > 0) out[0] = tv;
        int tag = ti;
        for (int t = LEN - 1; t >= 0; t--) {
            if (1 + t < out_cap) out[1 + t] = (float)tag;
            tag = bp[t][tag];
        }
    }
}

// ================= launch =================
extern "C" void kernel_launch(void* const* d_in, const int* in_sizes, int n_in,
                              void* d_out, int out_size)
{
    const int*   sentence = (const int*)  d_in[0];
    const float* embed    = (const float*)d_in[1];
    const float* w_ih_f   = (const float*)d_in[2];
    const float* w_hh_f   = (const float*)d_in[3];
    const float* b_ih_f   = (const float*)d_in[4];
    const float* b_hh_f   = (const float*)d_in[5];
    const float* w_ih_b   = (const float*)d_in[6];
    const float* w_hh_b   = (const float*)d_in[7];
    const float* b_ih_b   = (const float*)d_in[8];
    const float* b_hh_b   = (const float*)d_in[9];
    const float* w_out    = (const float*)d_in[10];
    const float* b_out    = (const float*)d_in[11];
    const float* trans    = (const float*)d_in[12];

    int out_cap = out_size < (LEN + 1) ? out_size : (LEN + 1);
    const int vit_smem = LEN * NTAG * (int)sizeof(float);   // 98,304 B

    cudaFuncSetAttribute(viterbi_kernel,
                         cudaFuncAttributeMaxDynamicSharedMemorySize, vit_smem);

    xg_gemm<<<dim3(LEN / 64, G4 / 64, 2), 256>>>(sentence, embed,
                                                 w_ih_f, w_ih_b,
                                                 b_ih_f, b_hh_f, b_ih_b, b_hh_b);
    lstm_kernel<<<16, 512>>>(w_hh_f, w_hh_b);
    feats_kernel<<<LEN / 16, 256>>>(w_out, b_out);
    viterbi_kernel<<<1, 32, vit_smem>>>(trans, (float*)d_out, out_cap);
}